// round 1
// baseline (speedup 1.0000x reference)
#include <cuda_runtime.h>
#include <cuda_bf16.h>
#include <math.h>
#include <stdint.h>

#define NUM_BINS   256
#define BITMAP_WORDS 2048            // 65536 bins / 32 bits
#define K1_BLOCKS  444               // 3 CTAs/SM * 148 SMs (64KB smem each, 192KB/SM)
#define K1_THREADS 256
#define SMEM_BYTES 65536             // 256*256 occupancy byte map

__device__ unsigned int g_bitmap[BITMAP_WORDS];

// ---------------------------------------------------------------------------
// k0: zero the global bitmap (must precede k1 on every graph replay)
// ---------------------------------------------------------------------------
__global__ void k0_zero()
{
    int t = blockIdx.x * blockDim.x + threadIdx.x;
    for (int w = t; w < BITMAP_WORDS; w += gridDim.x * blockDim.x)
        g_bitmap[w] = 0u;
}

// ---------------------------------------------------------------------------
// k1: per-CTA shared byte occupancy map, then pack->bits->atomicOr to global
// ---------------------------------------------------------------------------
__device__ __forceinline__ int to_bin(float v)
{
    // clip(v*255, 0, 255) then truncate-toward-zero (matches jnp clip+astype)
    float s = fminf(fmaxf(v * 255.0f, 0.0f), 255.0f);
    return (int)s;
}

extern "C" __global__ void __launch_bounds__(K1_THREADS, 3)
k1_hist(const float* __restrict__ X, const float* __restrict__ Y, int n)
{
    extern __shared__ unsigned char occ[];   // 65536 bytes

    // zero shared occupancy (as uint4: 4096 * 16B)
    uint4* occ4 = reinterpret_cast<uint4*>(occ);
    #pragma unroll
    for (int i = threadIdx.x; i < SMEM_BYTES / 16; i += K1_THREADS)
        occ4[i] = make_uint4(0u, 0u, 0u, 0u);
    __syncthreads();

    const int n4 = n >> 2;
    const float4* X4 = reinterpret_cast<const float4*>(X);
    const float4* Y4 = reinterpret_cast<const float4*>(Y);
    const int stride = gridDim.x * blockDim.x;

    for (int i = blockIdx.x * blockDim.x + threadIdx.x; i < n4; i += stride) {
        float4 x = X4[i];
        float4 y = Y4[i];
        occ[(to_bin(x.x) << 8) | to_bin(y.x)] = 1;
        occ[(to_bin(x.y) << 8) | to_bin(y.y)] = 1;
        occ[(to_bin(x.z) << 8) | to_bin(y.z)] = 1;
        occ[(to_bin(x.w) << 8) | to_bin(y.w)] = 1;
    }

    // scalar tail (handled by block 0 only)
    if (blockIdx.x == 0) {
        int tail = n & 3;
        int base = n - tail;
        if (threadIdx.x < tail) {
            int i = base + threadIdx.x;
            occ[(to_bin(X[i]) << 8) | to_bin(Y[i])] = 1;
        }
    }
    __syncthreads();

    // pack bytes -> bits, OR into the global bitmap
    const unsigned int* occ32 = reinterpret_cast<const unsigned int*>(occ);
    for (int w = threadIdx.x; w < BITMAP_WORDS; w += K1_THREADS) {
        unsigned int word = 0u;
        #pragma unroll
        for (int k = 0; k < 8; ++k) {
            unsigned int v = occ32[w * 8 + k];
            if (v & 0x000000FFu) word |= 1u << (4 * k + 0);
            if (v & 0x0000FF00u) word |= 1u << (4 * k + 1);
            if (v & 0x00FF0000u) word |= 1u << (4 * k + 2);
            if (v & 0xFF000000u) word |= 1u << (4 * k + 3);
        }
        if (word) atomicOr(&g_bitmap[w], word);
    }
}

// ---------------------------------------------------------------------------
// k2: single block. N, row/col counts, MI, 1 - tanh(mi)
//     bin index = bx*256 + by  -> word bx*8 + (by>>5), bit (by&31)
// ---------------------------------------------------------------------------
__global__ void __launch_bounds__(256, 1)
k2_mi(float* __restrict__ out)
{
    __shared__ unsigned int sbm[BITMAP_WORDS];
    __shared__ int   rowc[NUM_BINS];
    __shared__ float pyv[NUM_BINS];
    __shared__ int   sN;
    __shared__ double part[256];

    const int t = threadIdx.x;
    if (t == 0) sN = 0;
    #pragma unroll
    for (int w = t; w < BITMAP_WORDS; w += 256)
        sbm[w] = g_bitmap[w];
    __syncthreads();

    // row counts (thread t = row t): words t*8 .. t*8+7
    unsigned int rw[8];
    int rc = 0;
    #pragma unroll
    for (int k = 0; k < 8; ++k) { rw[k] = sbm[t * 8 + k]; rc += __popc(rw[k]); }
    rowc[t] = rc;
    atomicAdd(&sN, rc);

    // column counts (thread t = column t)
    {
        int wo = t >> 5, sh = t & 31;
        int cc = 0;
        #pragma unroll 8
        for (int bx = 0; bx < NUM_BINS; ++bx)
            cc += (sbm[bx * 8 + wo] >> sh) & 1;
        __syncthreads();                 // sN complete before read below
        float invNf = 1.0f / (float)sN;
        pyv[t] = (float)cc * invNf;
        __syncthreads();

        // MI: thread t handles row t; bitmap words already in registers rw[]
        float invN   = invNf;
        float pxf    = (float)rowc[t] * invNf;
        float logInv = __logf(invN);
        double mi = 0.0;
        #pragma unroll 8
        for (int j = 0; j < NUM_BINS; ++j) {
            if ((rw[j >> 5] >> (j & 31)) & 1u) {
                float d = fmaf(pxf, pyv[j], 1e-10f);
                // h * log(h / d) = invN * (log(invN) - log(d))
                mi += (double)(invN * (logInv - __logf(d)));
            }
        }
        part[t] = mi;
    }
    __syncthreads();

    for (int s = 128; s > 0; s >>= 1) {
        if (t < s) part[t] += part[t + s];
        __syncthreads();
    }
    if (t == 0)
        out[0] = (float)(1.0 - tanh(part[0]));
}

// ---------------------------------------------------------------------------
extern "C" void kernel_launch(void* const* d_in, const int* in_sizes, int n_in,
                              void* d_out, int out_size)
{
    const float* X = (const float*)d_in[0];   // I_complementary
    const float* Y = (const float*)d_in[1];   // I_target
    float* out = (float*)d_out;
    int n = in_sizes[0];

    // 64KB dynamic smem opt-in (idempotent; safe during capture — not a stream op)
    cudaFuncSetAttribute(k1_hist, cudaFuncAttributeMaxDynamicSharedMemorySize,
                         SMEM_BYTES);

    k0_zero<<<8, 256>>>();
    k1_hist<<<K1_BLOCKS, K1_THREADS, SMEM_BYTES>>>(X, Y, n);
    k2_mi<<<1, 256>>>(out);
}

// round 3
// speedup vs baseline: 1.1299x; 1.1299x over previous
#include <cuda_runtime.h>
#include <cuda_bf16.h>
#include <math.h>
#include <stdint.h>

#define NUM_BINS     256
#define BITMAP_WORDS 2048            // 65536 bins / 32 bits
#define K1_BLOCKS    296             // 2 CTAs/SM * 148 SMs
#define K1_THREADS   512
#define SMEM_BYTES   65536           // 256*256 occupancy byte map

__device__ unsigned int g_bitmap[BITMAP_WORDS];   // zero at module load; kernel re-zeroes at end
__device__ unsigned int g_done;                   // ticket counter, reset at end

__device__ __forceinline__ int to_bin(float v)
{
    float s = fminf(fmaxf(v * 255.0f, 0.0f), 255.0f);
    return (int)s;   // truncation matches jnp clip+astype(int32)
}

__device__ __forceinline__ void mark4(unsigned char* occ, float4 x, float4 y)
{
    occ[(to_bin(x.x) << 8) | to_bin(y.x)] = 1;
    occ[(to_bin(x.y) << 8) | to_bin(y.y)] = 1;
    occ[(to_bin(x.z) << 8) | to_bin(y.z)] = 1;
    occ[(to_bin(x.w) << 8) | to_bin(y.w)] = 1;
}

extern "C" __global__ void __launch_bounds__(K1_THREADS, 2)
mi_fused(const float* __restrict__ X, const float* __restrict__ Y, int n,
         float* __restrict__ out)
{
    extern __shared__ unsigned char occ[];   // 65536 bytes
    __shared__ unsigned s_ticket;

    const int t = threadIdx.x;

    // ---- zero shared occupancy map (uint4, conflict-free) ----
    uint4* occ4 = reinterpret_cast<uint4*>(occ);
    #pragma unroll
    for (int i = t; i < SMEM_BYTES / 16; i += K1_THREADS)
        occ4[i] = make_uint4(0u, 0u, 0u, 0u);
    __syncthreads();

    // ---- bulk phase: 4-way unrolled grid-stride, 8 LDG.128 front-batched ----
    const int n4 = n >> 2;
    const float4* X4 = reinterpret_cast<const float4*>(X);
    const float4* Y4 = reinterpret_cast<const float4*>(Y);
    const int stride = gridDim.x * blockDim.x;
    int i = blockIdx.x * blockDim.x + t;

    for (; i + 3 * stride < n4; i += 4 * stride) {
        float4 x0 = X4[i];              float4 x1 = X4[i + stride];
        float4 x2 = X4[i + 2 * stride]; float4 x3 = X4[i + 3 * stride];
        float4 y0 = Y4[i];              float4 y1 = Y4[i + stride];
        float4 y2 = Y4[i + 2 * stride]; float4 y3 = Y4[i + 3 * stride];
        mark4(occ, x0, y0); mark4(occ, x1, y1);
        mark4(occ, x2, y2); mark4(occ, x3, y3);
    }
    for (; i < n4; i += stride) {
        float4 x = X4[i]; float4 y = Y4[i];
        mark4(occ, x, y);
    }
    if (blockIdx.x == 0) {              // scalar tail
        int tail = n & 3, base = n - tail;
        if (t < tail)
            occ[(to_bin(X[base + t]) << 8) | to_bin(Y[base + t])] = 1;
    }
    __syncthreads();

    // ---- pack bytes -> bits (bank-conflict-free via rotated byte-group order) ----
    const unsigned int* occ32 = reinterpret_cast<const unsigned int*>(occ);
    const int rot = (t >> 2) & 7;
    #pragma unroll
    for (int w = t; w < BITMAP_WORDS; w += K1_THREADS) {
        unsigned int word = 0u;
        #pragma unroll
        for (int k = 0; k < 8; ++k) {
            int k2 = (k + rot) & 7;
            unsigned int v = occ32[w * 8 + k2];          // bytes are exactly 0 or 1
            unsigned int nib = (v | (v >> 7) | (v >> 14) | (v >> 21)) & 0xFu;
            word |= nib << (4 * k2);
        }
        if (word) atomicOr(&g_bitmap[w], word);
    }

    // ---- last-block election (release/acquire) ----
    __threadfence();
    __syncthreads();
    if (t == 0) s_ticket = atomicAdd(&g_done, 1u);
    __syncthreads();
    if (s_ticket != (unsigned)(gridDim.x - 1)) return;
    __threadfence();

    // ================= epilogue (last CTA only) =================
    // carve scratch from the dynamic smem (occ map no longer needed)
    unsigned int* sbm  = reinterpret_cast<unsigned int*>(occ);          // 8192 B
    int*          rowc = reinterpret_cast<int*>(occ + 8192);            // 1024 B
    float*        pyv  = reinterpret_cast<float*>(occ + 9216);          // 1024 B
    double*       part = reinterpret_cast<double*>(occ + 10240);        // 2048 B
    int*          sN   = reinterpret_cast<int*>(occ + 12288);

    __syncthreads();                    // everyone past the occ32 reads above
    if (t == 0) *sN = 0;
    #pragma unroll
    for (int w = t; w < BITMAP_WORDS; w += K1_THREADS) {
        sbm[w] = g_bitmap[w];
        g_bitmap[w] = 0u;               // reset for the next graph replay
    }
    __syncthreads();

    unsigned int rw[8];
    if (t < NUM_BINS) {                 // thread t = row t
        int rc = 0;
        #pragma unroll
        for (int k = 0; k < 8; ++k) { rw[k] = sbm[t * 8 + k]; rc += __popc(rw[k]); }
        rowc[t] = rc;
        atomicAdd(sN, rc);
    }
    __syncthreads();

    float invN = 1.0f / (float)(*sN);

    if (t < NUM_BINS) {                 // thread t = column t
        int wo = t >> 5, sh = t & 31;
        int cc = 0;
        #pragma unroll 8
        for (int bx = 0; bx < NUM_BINS; ++bx)
            cc += (sbm[bx * 8 + wo] >> sh) & 1;
        pyv[t] = (float)cc * invN;
    }
    __syncthreads();

    if (t < NUM_BINS) {                 // MI contribution of row t
        float pxf    = (float)rowc[t] * invN;
        float logInv = __logf(invN);
        double mi = 0.0;
        #pragma unroll 8
        for (int j = 0; j < NUM_BINS; ++j) {
            if ((rw[j >> 5] >> (j & 31)) & 1u) {
                float d = fmaf(pxf, pyv[j], 1e-10f);
                mi += (double)(invN * (logInv - __logf(d)));   // h*log(h/denom)
            }
        }
        part[t] = mi;
    }
    __syncthreads();

    for (int s = 128; s > 0; s >>= 1) {
        if (t < s) part[t] += part[t + s];
        __syncthreads();
    }
    if (t == 0) {
        out[0] = (float)(1.0 - tanh(part[0]));
        g_done = 0u;                    // reset ticket for next replay
    }
}

extern "C" void kernel_launch(void* const* d_in, const int* in_sizes, int n_in,
                              void* d_out, int out_size)
{
    const float* X = (const float*)d_in[0];   // I_complementary
    const float* Y = (const float*)d_in[1];   // I_target
    float* out = (float*)d_out;
    int n = in_sizes[0];

    static bool attr_done = false;
    if (!attr_done) {
        cudaFuncSetAttribute(mi_fused, cudaFuncAttributeMaxDynamicSharedMemorySize,
                             SMEM_BYTES);
        attr_done = true;
    }
    mi_fused<<<K1_BLOCKS, K1_THREADS, SMEM_BYTES>>>(X, Y, n, out);
}